// round 15
// baseline (speedup 1.0000x reference)
#include <cuda_runtime.h>
#include <cuda_fp16.h>
#include <math.h>
#include <stdint.h>

// Problem constants
#define Bn    128
#define HIDD  64
#define INDIM 2
#define CX    66
#define NN    1024
#define MROWS (Bn * CX)       // 8448
#define NWIDE 4096            // combined output width

// ---------------- scratch (device globals) ----------------
__device__ __half g_X [MROWS * NN];            // X / Xc (fp16)
__device__ __half g_P [MROWS * NWIDE];         // [P1|P2|P3|P4]
__device__ __half g_B [NWIDE * NN];            // rows: A0 | 2A0^2-I | A1 | 2A1^2-I
__device__ __half g_At[2 * NN * NN];           // 2*A^T per adjacency
__device__ __half g_U [Bn * HIDD * NN];        // u gate fp16
__device__ __half g_Wru[128 * 336];
__device__ __half g_WC [64 * 336];

// ---------------- PTX helpers (base ISA only) ----------------
__device__ __forceinline__ uint32_t smem_u32(const void* p) {
    uint32_t a;
    asm("{ .reg .u64 t; cvta.to.shared.u64 t, %1; cvt.u32.u64 %0, t; }" : "=r"(a) : "l"(p));
    return a;
}
__device__ __forceinline__ void cp16(uint32_t dst, const void* src) {
    asm volatile("cp.async.cg.shared.global [%0], [%1], 16;" :: "r"(dst), "l"(src) : "memory");
}
__device__ __forceinline__ void ldm_x4(uint32_t* r, uint32_t a) {
    asm volatile("ldmatrix.sync.aligned.m8n8.x4.shared.b16 {%0,%1,%2,%3}, [%4];"
                 : "=r"(r[0]), "=r"(r[1]), "=r"(r[2]), "=r"(r[3]) : "r"(a));
}
__device__ __forceinline__ void ldm_x4t(uint32_t* r, uint32_t a) {
    asm volatile("ldmatrix.sync.aligned.m8n8.x4.trans.shared.b16 {%0,%1,%2,%3}, [%4];"
                 : "=r"(r[0]), "=r"(r[1]), "=r"(r[2]), "=r"(r[3]) : "r"(a));
}
__device__ __forceinline__ void mma16816(float* c, const uint32_t* a, const uint32_t* b) {
    asm volatile("mma.sync.aligned.m16n8k16.row.col.f32.f16.f16.f32 "
                 "{%0,%1,%2,%3},{%4,%5,%6,%7},{%8,%9},{%0,%1,%2,%3};"
                 : "+f"(c[0]), "+f"(c[1]), "+f"(c[2]), "+f"(c[3])
                 : "r"(a[0]), "r"(a[1]), "r"(a[2]), "r"(a[3]), "r"(b[0]), "r"(b[1]));
}

// shared GEMM geometry
#define MB 128
#define NT 16
#define STG_BYTES 32768
#define SM_TOT (3 * STG_BYTES)

// ============================================================
// sq_gemm: g_B[seg 2z+1] = 2*A_z^2 - I
// ============================================================
__global__ void __launch_bounds__(256, 2)
sq_gemm()
{
    extern __shared__ char smem[];
    const uint32_t sb = smem_u32(smem);
    const int tid  = threadIdx.x;
    const int lane = tid & 31;
    const int wid  = tid >> 5;
    const int wm   = wid & 3;
    const int wn   = wid >> 2;
    const int bm   = blockIdx.y * MB;
    const int bn   = blockIdx.x * MB;
    const int z    = blockIdx.z;

    const __half* Xin = g_B  + (size_t)z * 2048 * NN;
    const __half* Ain = g_At + (size_t)z * NN * NN;
    __half* Out = g_B + ((size_t)z * 2048 + 1024) * NN;

    float acc[2][8][4];
#pragma unroll
    for (int t2 = 0; t2 < 2; t2++)
#pragma unroll
        for (int j = 0; j < 8; j++)
#pragma unroll
            for (int e = 0; e < 4; e++) acc[t2][j][e] = 0.0f;

    auto fill = [&](int t) {
        const int kt = t * 64;
        const uint32_t sa = sb + (t % 3) * STG_BYTES;
        const uint32_t sB = sa + 16384;
#pragma unroll
        for (int j = 0; j < 4; j++) {
            const int u = tid + j * 256;
            const int row = u >> 3, ch = u & 7;
            cp16(sa + row * 128 + ((ch ^ (row & 7)) << 4),
                 Xin + (size_t)(bm + row) * NN + kt + ch * 8);
        }
#pragma unroll
        for (int j = 0; j < 4; j++) {
            const int u = tid + j * 256;
            const int row = u >> 3, ch = u & 7;
            cp16(sB + row * 128 + ((ch ^ (row & 7)) << 4),
                 Ain + (size_t)(bn + row) * NN + kt + ch * 8);
        }
        asm volatile("cp.async.commit_group;" ::: "memory");
    };

    const int arow_l = (lane & 15);
    const int ach_l  = (lane >> 4);
    const int bgrp   = lane >> 3;
    const int brow_l = (lane & 7) + ((bgrp >> 1) << 3);
    const int bch_l  = (bgrp & 1);

    fill(0); fill(1);
    for (int t = 0; t < NT; t++) {
        if (t < NT - 1) asm volatile("cp.async.wait_group 1;" ::: "memory");
        else            asm volatile("cp.async.wait_group 0;" ::: "memory");
        __syncthreads();
        if (t + 2 < NT) fill(t + 2);

        const uint32_t sa = sb + (t % 3) * STG_BYTES;
        const uint32_t sB = sa + 16384;
#pragma unroll
        for (int ks = 0; ks < 4; ks++) {
            uint32_t afr[2][4];
#pragma unroll
            for (int t2 = 0; t2 < 2; t2++) {
                const int row = wm * 32 + t2 * 16 + arow_l;
                const int ch  = 2 * ks + ach_l;
                ldm_x4(afr[t2], sa + row * 128 + ((ch ^ (row & 7)) << 4));
            }
            uint32_t bfr[4][4];
#pragma unroll
            for (int tn = 0; tn < 4; tn++) {
                const int row = wn * 64 + tn * 16 + brow_l;
                const int ch  = 2 * ks + bch_l;
                ldm_x4(bfr[tn], sB + row * 128 + ((ch ^ (row & 7)) << 4));
            }
#pragma unroll
            for (int t2 = 0; t2 < 2; t2++)
#pragma unroll
                for (int j = 0; j < 8; j++)
                    mma16816(acc[t2][j], afr[t2], &bfr[j >> 1][(j & 1) * 2]);
        }
    }

    const int g  = lane >> 2;
    const int c2 = (lane & 3) * 2;
#pragma unroll
    for (int t2 = 0; t2 < 2; t2++)
#pragma unroll
        for (int j = 0; j < 8; j++) {
            const int col = bn + wn * 64 + j * 8 + c2;
#pragma unroll
            for (int half = 0; half < 2; half++) {
                const int row = bm + wm * 32 + t2 * 16 + g + half * 8;
                float v0 = acc[t2][j][half * 2 + 0];
                float v1 = acc[t2][j][half * 2 + 1];
                if (row == col)     v0 -= 1.0f;     // fold -I
                if (row == col + 1) v1 -= 1.0f;
                union { uint32_t u; __half h[2]; } Oh;
                Oh.h[0] = __float2half_rn(v0);
                Oh.h[1] = __float2half_rn(v1);
                *(uint32_t*)(Out + (size_t)row * NN + col) = Oh.u;
            }
        }
}

// ============================================================
// Wide GEMM into g_P — 4 warps (128 thr), warp tile 64x64.
// PART=0: segs {0,2}, grid (16,66). PART=1: segs {1,3}, grid (16,66).
// PART=2: all segs, grid (32,66).
// ============================================================
template<int PART>
__global__ void __launch_bounds__(128, 2)
gemm_wide(const __half* __restrict__ Xin, __half* __restrict__ Out)
{
    extern __shared__ char smem[];
    const uint32_t sb = smem_u32(smem);
    const int tid  = threadIdx.x;
    const int lane = tid & 31;
    const int wid  = tid >> 5;
    const int wm   = wid & 1;
    const int wn   = wid >> 1;
    const int bm   = blockIdx.y * MB;

    int bnG;
    if (PART == 0)      bnG = (blockIdx.x >> 3) * 2048 + (blockIdx.x & 7) * 128;
    else if (PART == 1) bnG = (blockIdx.x >> 3) * 2048 + 1024 + (blockIdx.x & 7) * 128;
    else                bnG = blockIdx.x * 128;

    float acc[4][8][4];
#pragma unroll
    for (int tm = 0; tm < 4; tm++)
#pragma unroll
        for (int j = 0; j < 8; j++)
#pragma unroll
            for (int e = 0; e < 4; e++) acc[tm][j][e] = 0.0f;

    auto fill = [&](int t) {
        const int kt = t * 64;
        const uint32_t sa = sb + (t % 3) * STG_BYTES;
        const uint32_t sB = sa + 16384;
#pragma unroll
        for (int j = 0; j < 8; j++) {
            const int u = tid + j * 128;
            const int row = u >> 3, ch = u & 7;
            cp16(sa + row * 128 + ((ch ^ (row & 7)) << 4),
                 Xin + (size_t)(bm + row) * NN + kt + ch * 8);
        }
#pragma unroll
        for (int j = 0; j < 8; j++) {
            const int u = tid + j * 128;
            const int row = u >> 3, ch = u & 7;
            cp16(sB + row * 128 + ((ch ^ (row & 7)) << 4),
                 g_B + (size_t)(bnG + row) * NN + kt + ch * 8);
        }
        asm volatile("cp.async.commit_group;" ::: "memory");
    };

    const int arow_l = (lane & 15);
    const int ach_l  = (lane >> 4);
    const int bgrp   = lane >> 3;
    const int brow_l = (lane & 7) + ((bgrp >> 1) << 3);
    const int bch_l  = (bgrp & 1);

    fill(0); fill(1);
    for (int t = 0; t < NT; t++) {
        if (t < NT - 1) asm volatile("cp.async.wait_group 1;" ::: "memory");
        else            asm volatile("cp.async.wait_group 0;" ::: "memory");
        __syncthreads();
        if (t + 2 < NT) fill(t + 2);

        const uint32_t sa = sb + (t % 3) * STG_BYTES;
        const uint32_t sB = sa + 16384;
#pragma unroll
        for (int ks = 0; ks < 4; ks++) {
            uint32_t afr[4][4];
#pragma unroll
            for (int tm = 0; tm < 4; tm++) {
                const int row = wm * 64 + tm * 16 + arow_l;
                const int ch  = 2 * ks + ach_l;
                ldm_x4(afr[tm], sa + row * 128 + ((ch ^ (row & 7)) << 4));
            }
            uint32_t bfr[4][4];
#pragma unroll
            for (int tn = 0; tn < 4; tn++) {
                const int row = wn * 64 + tn * 16 + brow_l;
                const int ch  = 2 * ks + bch_l;
                ldm_x4(bfr[tn], sB + row * 128 + ((ch ^ (row & 7)) << 4));
            }
#pragma unroll
            for (int tm = 0; tm < 4; tm++)
#pragma unroll
                for (int j = 0; j < 8; j++)
                    mma16816(acc[tm][j], afr[tm], &bfr[j >> 1][(j & 1) * 2]);
        }
    }

    const int g  = lane >> 2;
    const int c2 = (lane & 3) * 2;
#pragma unroll
    for (int tm = 0; tm < 4; tm++)
#pragma unroll
        for (int j = 0; j < 8; j++) {
            const int col = bnG + wn * 64 + j * 8 + c2;
#pragma unroll
            for (int half = 0; half < 2; half++) {
                const int row = bm + wm * 64 + tm * 16 + g + half * 8;
                union { uint32_t u; __half h[2]; } Oh;
                Oh.h[0] = __float2half_rn(acc[tm][j][half * 2 + 0]);
                Oh.h[1] = __float2half_rn(acc[tm][j][half * 2 + 1]);
                *(uint32_t*)(Out + (size_t)row * NWIDE + col) = Oh.u;
            }
        }
}

// ============================================================
// Projection via fp16 HMMA, K=336. Triple-buffer, 1 sync/iter.
// ============================================================
#define PKT 48
#define PNT 7
#define CSTR 132

template<int OTILE, int MODE>
__global__ void __launch_bounds__(256, 2)
proj_mma(const __half* __restrict__ Wsp, const float* __restrict__ bias,
         const __half* __restrict__ Xbase, const __half* __restrict__ Pbase,
         const __half* __restrict__ Uin, const float* __restrict__ hx,
         __half* __restrict__ Xout, __half* __restrict__ Uout,
         float* __restrict__ outp)
{
    constexpr int HS_B = PKT * 256;
    constexpr int WS_B = OTILE * 128;
    constexpr int STGP = HS_B + WS_B;
    constexpr int OW   = OTILE / 2;
    constexpr int NJ   = OW / 8;

    extern __shared__ char smem[];
    const uint32_t sb = smem_u32(smem);
    float* Cs = (float*)smem;

    const int tid  = threadIdx.x;
    const int lane = tid & 31;
    const int wid  = tid >> 5;
    const int wm   = wid & 3;
    const int wn   = wid >> 2;
    const int b    = blockIdx.y;
    const int bn0  = blockIdx.x * 128;

    float acc[2][NJ][4];
#pragma unroll
    for (int t2 = 0; t2 < 2; t2++)
#pragma unroll
        for (int j = 0; j < NJ; j++)
#pragma unroll
            for (int e = 0; e < 4; e++) acc[t2][j][e] = 0.0f;

    auto fill = [&](int t) {
        const int kt = t * PKT;
        const uint32_t hs = sb + (t % 3) * STGP;
        const uint32_t ws = hs + HS_B;
#pragma unroll
        for (int j = 0; j < 3; j++) {
            const int u = tid + j * 256;
            const int r = u >> 4, ch = u & 15;
            int c = kt + r;
            if (c >= 330) c = 0;
            const int p  = c / 66;
            const int cc = c - p * 66;
            const __half* gsrc;
            if (p == 0)
                gsrc = Xbase + ((size_t)b * CX + cc) * NN + bn0 + ch * 8;
            else
                gsrc = Pbase + ((size_t)b * CX + cc) * NWIDE + (size_t)(p - 1) * 1024
                     + bn0 + ch * 8;
            cp16(hs + r * 256 + ((ch ^ (r & 15)) << 4), gsrc);
        }
#pragma unroll
        for (int j = 0; j < (OTILE * 6 + 255) / 256; j++) {
            const int u = tid + j * 256;
            if (u < OTILE * 6) {
                const int orow = u / 6, wc = u - orow * 6;
                cp16(ws + orow * 128 + ((wc ^ (orow & 7)) << 4),
                     Wsp + (size_t)orow * 336 + kt + wc * 8);
            }
        }
        asm volatile("cp.async.commit_group;" ::: "memory");
    };

    const int krow_l = (lane & 7) + ((lane >> 4) << 3);
    const int m8sel  = (lane >> 3) & 1;
    const int bgrp   = lane >> 3;
    const int brow_l = (lane & 7) + ((bgrp >> 1) << 3);
    const int bch_l  = (bgrp & 1);

    fill(0); fill(1);
    for (int t = 0; t < PNT; t++) {
        if (t < PNT - 1) asm volatile("cp.async.wait_group 1;" ::: "memory");
        else             asm volatile("cp.async.wait_group 0;" ::: "memory");
        __syncthreads();
        if (t + 2 < PNT) fill(t + 2);

        const uint32_t hs = sb + (t % 3) * STGP;
        const uint32_t ws = hs + HS_B;
#pragma unroll
        for (int ks = 0; ks < 3; ks++) {
            uint32_t afr[2][4];
#pragma unroll
            for (int t2 = 0; t2 < 2; t2++) {
                const int kr  = ks * 16 + krow_l;
                const int chm = (wm * 4) + (t2 * 2) + m8sel;
                ldm_x4t(afr[t2], hs + kr * 256 + ((chm ^ (kr & 15)) << 4));
            }
            uint32_t bfr[NJ / 2 > 0 ? NJ / 2 : 1][4];
#pragma unroll
            for (int tn = 0; tn < NJ / 2; tn++) {
                const int row = wn * OW + tn * 16 + brow_l;
                const int ch  = 2 * ks + bch_l;
                ldm_x4(bfr[tn], ws + row * 128 + ((ch ^ (row & 7)) << 4));
            }
#pragma unroll
            for (int t2 = 0; t2 < 2; t2++)
#pragma unroll
                for (int j = 0; j < NJ; j++)
                    mma16816(acc[t2][j], afr[t2], &bfr[j >> 1][(j & 1) * 2]);
        }
    }

    __syncthreads();
    const int g  = lane >> 2;
    const int c2 = (lane & 3) * 2;
#pragma unroll
    for (int t2 = 0; t2 < 2; t2++)
#pragma unroll
        for (int j = 0; j < NJ; j++)
#pragma unroll
            for (int e = 0; e < 4; e++) {
                const int n = wm * 32 + t2 * 16 + g + (e >> 1) * 8;
                const int o = wn * OW + j * 8 + c2 + (e & 1);
                Cs[o * CSTR + n] = acc[t2][j][e];
            }
    __syncthreads();

    for (int o = wid; o < OTILE; o += 8) {
        const float bv = bias[o];
        const int n = lane * 4;
        float4 v = *(float4*)&Cs[o * CSTR + n];
        if (MODE == 0) {
            v.x = 1.0f / (1.0f + expf(-(v.x + bv)));
            v.y = 1.0f / (1.0f + expf(-(v.y + bv)));
            v.z = 1.0f / (1.0f + expf(-(v.z + bv)));
            v.w = 1.0f / (1.0f + expf(-(v.w + bv)));
            union { uint2 u2; __half h[4]; } O;
            if (o < HIDD) {
                const float4 h4 = *(const float4*)(hx + ((size_t)b * HIDD + o) * NN + bn0 + n);
                O.h[0] = __float2half_rn(v.x * h4.x);
                O.h[1] = __float2half_rn(v.y * h4.y);
                O.h[2] = __float2half_rn(v.z * h4.z);
                O.h[3] = __float2half_rn(v.w * h4.w);
                *(uint2*)(Xout + ((size_t)b * CX + INDIM + o) * NN + bn0 + n) = O.u2;
            } else {
                O.h[0] = __float2half_rn(v.x);
                O.h[1] = __float2half_rn(v.y);
                O.h[2] = __float2half_rn(v.z);
                O.h[3] = __float2half_rn(v.w);
                *(uint2*)(Uout + ((size_t)b * HIDD + (o - HIDD)) * NN + bn0 + n) = O.u2;
            }
        } else {
            union { uint2 u2; __half h[4]; } U;
            U.u2 = *(const uint2*)(Uin + ((size_t)b * HIDD + o) * NN + bn0 + n);
            const float4 h4 = *(const float4*)(hx + ((size_t)b * HIDD + o) * NN + bn0 + n);
            float4 r;
            const float u0 = __half2float(U.h[0]);
            const float u1 = __half2float(U.h[1]);
            const float u2 = __half2float(U.h[2]);
            const float u3 = __half2float(U.h[3]);
            r.x = u0 * h4.x + (1.0f - u0) * tanhf(v.x + bv);
            r.y = u1 * h4.y + (1.0f - u1) * tanhf(v.y + bv);
            r.z = u2 * h4.z + (1.0f - u2) * tanhf(v.z + bv);
            r.w = u3 * h4.w + (1.0f - u3) * tanhf(v.w + bv);
            *(float4*)(outp + ((size_t)b * HIDD + o) * NN + bn0 + n) = r;
        }
    }
}

// ============================================================
// prep kernels
// ============================================================
__global__ void prepA_kernel(const float* __restrict__ A0, const float* __restrict__ A1)
{
    __shared__ float ts[32][33];
    const int adj = blockIdx.z;
    const float* A = adj ? A1 : A0;
    const int x0 = blockIdx.x * 32;
    const int y0 = blockIdx.y * 32;
#pragma unroll
    for (int i = 0; i < 4; i++) {
        const int r = y0 + threadIdx.y + i * 8;
        const float v = A[(size_t)r * NN + x0 + threadIdx.x];
        ts[threadIdx.y + i * 8][threadIdx.x] = v;
        g_B[((size_t)adj * 2048 + r) * NN + x0 + threadIdx.x] = __float2half_rn(v);
    }
    __syncthreads();
#pragma unroll
    for (int i = 0; i < 4; i++) {
        const int r = x0 + threadIdx.y + i * 8;
        g_At[((size_t)adj * NN + r) * NN + y0 + threadIdx.x] =
            __float2half_rn(2.0f * ts[threadIdx.x][threadIdx.y + i * 8]);
    }
}

#define PK_ITEMS (MROWS * 256)
#define W_ITEMS  (192 * 336)

__global__ void pack1_kernel(const float* __restrict__ inputs, const float* __restrict__ hx,
                             const float* __restrict__ W_ru, const float* __restrict__ W_C)
{
    const int idx = blockIdx.x * blockDim.x + threadIdx.x;
    if (idx < PK_ITEMS) {
        const int n4 = idx & 255;
        const int t  = idx >> 8;
        const int c  = t % CX;
        const int b  = t / CX;
        float4 v;
        if (c < INDIM)
            v = ((const float4*)inputs)[((size_t)b * INDIM + c) * 256 + n4];
        else
            v = ((const float4*)hx)[((size_t)b * HIDD + (c - INDIM)) * 256 + n4];
        union { uint2 u; __half h[4]; } H;
        H.h[0] = __float2half_rn(v.x);
        H.h[1] = __float2half_rn(v.y);
        H.h[2] = __float2half_rn(v.z);
        H.h[3] = __float2half_rn(v.w);
        *(uint2*)(g_X + (size_t)t * NN + n4 * 4) = H.u;
    } else if (idx < PK_ITEMS + W_ITEMS) {
        const int k = idx - PK_ITEMS;
        const int o = k / 336;
        const int c = k - o * 336;
        float w = 0.0f;
        if (c < 330) w = (o < 128) ? W_ru[(size_t)o * 330 + c] : W_C[(size_t)(o - 128) * 330 + c];
        const __half h = __float2half_rn(w);
        if (o < 128) g_Wru[(size_t)o * 336 + c] = h;
        else         g_WC[(size_t)(o - 128) * 336 + c] = h;
    }
}

// ============================================================
extern "C" void kernel_launch(void* const* d_in, const int* in_sizes, int n_in,
                              void* d_out, int out_size)
{
    const float* inputs = (const float*)d_in[0];
    const float* hx     = (const float*)d_in[1];
    const float* A0     = (const float*)d_in[2];
    const float* A1     = (const float*)d_in[3];
    const float* W_ru   = (const float*)d_in[4];
    const float* b_ru   = (const float*)d_in[5];
    const float* W_C    = (const float*)d_in[6];
    const float* b_C    = (const float*)d_in[7];
    float* out = (float*)d_out;

    __half *gX, *gP, *gU, *gWru, *gWC;
    cudaGetSymbolAddress((void**)&gX,  g_X);
    cudaGetSymbolAddress((void**)&gP,  g_P);
    cudaGetSymbolAddress((void**)&gU,  g_U);
    cudaGetSymbolAddress((void**)&gWru, g_Wru);
    cudaGetSymbolAddress((void**)&gWC,  g_WC);

    static bool attr_set = false;
    static cudaStream_t s1;
    static cudaEvent_t evFork, evPack, evG1;
    if (!attr_set) {
        cudaFuncSetAttribute(sq_gemm,      cudaFuncAttributeMaxDynamicSharedMemorySize, SM_TOT);
        cudaFuncSetAttribute(gemm_wide<0>, cudaFuncAttributeMaxDynamicSharedMemorySize, SM_TOT);
        cudaFuncSetAttribute(gemm_wide<1>, cudaFuncAttributeMaxDynamicSharedMemorySize, SM_TOT);
        cudaFuncSetAttribute(gemm_wide<2>, cudaFuncAttributeMaxDynamicSharedMemorySize, SM_TOT);
        const int p0 = 3 * (PKT * 256 + 128 * 128) > 128 * CSTR * 4
                     ? 3 * (PKT * 256 + 128 * 128) : 128 * CSTR * 4;       // 86016
        const int p1 = 3 * (PKT * 256 + 64 * 128) > 64 * CSTR * 4
                     ? 3 * (PKT * 256 + 64 * 128) : 64 * CSTR * 4;         // 61440
        cudaFuncSetAttribute(proj_mma<128, 0>, cudaFuncAttributeMaxDynamicSharedMemorySize, p0);
        cudaFuncSetAttribute(proj_mma<64, 1>,  cudaFuncAttributeMaxDynamicSharedMemorySize, p1);
        cudaStreamCreateWithFlags(&s1, cudaStreamNonBlocking);
        cudaEventCreateWithFlags(&evFork, cudaEventDisableTiming);
        cudaEventCreateWithFlags(&evPack, cudaEventDisableTiming);
        cudaEventCreateWithFlags(&evG1,   cudaEventDisableTiming);
        attr_set = true;
    }
    const int smem0 = 3 * (PKT * 256 + 128 * 128) > 128 * CSTR * 4
                    ? 3 * (PKT * 256 + 128 * 128) : 128 * CSTR * 4;
    const int smem1 = 3 * (PKT * 256 + 64 * 128) > 64 * CSTR * 4
                    ? 3 * (PKT * 256 + 64 * 128) : 64 * CSTR * 4;

    const int packBlocks = (PK_ITEMS + W_ITEMS + 255) / 256;

    // Fork: origin -> evFork -> s1 (canonical capture fork, no helper kernel).
    cudaEventRecord(evFork, 0);
    cudaStreamWaitEvent(s1, evFork, 0);

    // s1: prepA -> sq_gemm -> (wait pack) -> gw<1>      (segs 1,3)
    // main: pack1 -> gw<0>                               (segs 0,2)
    prepA_kernel<<<dim3(32, 32, 2), dim3(32, 8), 0, s1>>>(A0, A1);
    sq_gemm<<<dim3(8, 8, 2), 256, SM_TOT, s1>>>();

    pack1_kernel<<<packBlocks, 256>>>(inputs, hx, W_ru, W_C);
    cudaEventRecord(evPack, 0);
    cudaStreamWaitEvent(s1, evPack, 0);

    gemm_wide<1><<<dim3(16, MROWS / 128), 128, SM_TOT, s1>>>(gX, gP);
    cudaEventRecord(evG1, s1);

    // main: gw<0> (needs prepA; sq+gw<1> co-run on s1 — prepA is ordered
    // before sq on s1, and gw<0> also needs it: join via evG1 is too late,
    // so gw<0> must wait on an event after prepA. Use evG1 only for proj.
    // Simplest correct: gw<0> reads g_B segs {0,2} written by prepA. Order
    // main behind prepA via a dedicated event:
    //   (prepA is first on s1; we record no extra event — instead gw<0>
    //    waits on evG1? too late. So record evA right after prepA.)
    // NOTE: evPack wait above already serializes s1 behind pack1.
    // We add evA below.
    // ---- (launch ordering continues) ----
    static cudaEvent_t evA = nullptr;
    if (!evA) cudaEventCreateWithFlags(&evA, cudaEventDisableTiming);
    // Re-record prepA completion each call: s1 ops so far: prepA, sq, gw<1>.
    // evA must be recorded between prepA and sq — but launches above already
    // queued. To keep ordering simple and correct, make gw<0> wait on evG1's
    // predecessor chain via a second event recorded NOW on s1 (after gw<1>),
    // which would over-serialize. Instead: gw<0> waits on evPack (main-local,
    // no-op) AND we rely on prepA ordering by moving gw<0> BEHIND an event
    // recorded after prepA. Since we cannot insert retroactively, we instead
    // launch gw<0> on s1's sibling ordering: wait on evG1 is wrong; so the
    // robust fix is: gw<0> waits on an event recorded after prepA — handled
    // by re-structuring below on the NEXT call. For THIS call structure we
    // conservatively order gw<0> after sq via evSq-free approach:
    cudaStreamWaitEvent(0, evG1, 0);   // conservative join (prepA+sq+gw<1> done)
    gemm_wide<0><<<dim3(16, MROWS / 128), 128, SM_TOT>>>(gX, gP);

    // ---------- pass 1 projection: gates ----------
    proj_mma<128, 0><<<dim3(8, Bn), 256, smem0>>>(gWru, b_ru, gX, gP,
                                                  nullptr, hx, gX, gU, nullptr);

    // ---------- pass 2: candidate + output ----------
    gemm_wide<2><<<dim3(32, MROWS / 128), 128, SM_TOT>>>(gX, gP);
    proj_mma<64, 1><<<dim3(8, Bn), 256, smem1>>>(gWC, b_C, gX, gP,
                                                 gU, hx, nullptr, nullptr, out);
}

// round 16
// speedup vs baseline: 1.0654x; 1.0654x over previous
#include <cuda_runtime.h>
#include <cuda_fp16.h>
#include <math.h>
#include <stdint.h>

// Problem constants
#define Bn    128
#define HIDD  64
#define INDIM 2
#define CX    66
#define NN    1024
#define MROWS (Bn * CX)       // 8448
#define NWIDE 4096            // combined output width

// ---------------- scratch (device globals) ----------------
__device__ __half g_X [MROWS * NN];            // X / Xc (fp16)
__device__ __half g_P [MROWS * NWIDE];         // [P1|P2|P3|P4]
__device__ __half g_B [NWIDE * NN];            // rows: A0 | 2A0^2-I | A1 | 2A1^2-I
__device__ __half g_At[2 * NN * NN];           // 2*A^T per adjacency
__device__ __half g_U [Bn * HIDD * NN];        // u gate fp16
__device__ __half g_Wru[128 * 336];
__device__ __half g_WC [64 * 336];

// ---------------- PTX helpers (base ISA only) ----------------
__device__ __forceinline__ uint32_t smem_u32(const void* p) {
    uint32_t a;
    asm("{ .reg .u64 t; cvta.to.shared.u64 t, %1; cvt.u32.u64 %0, t; }" : "=r"(a) : "l"(p));
    return a;
}
__device__ __forceinline__ void cp16(uint32_t dst, const void* src) {
    asm volatile("cp.async.cg.shared.global [%0], [%1], 16;" :: "r"(dst), "l"(src) : "memory");
}
__device__ __forceinline__ void ldm_x4(uint32_t* r, uint32_t a) {
    asm volatile("ldmatrix.sync.aligned.m8n8.x4.shared.b16 {%0,%1,%2,%3}, [%4];"
                 : "=r"(r[0]), "=r"(r[1]), "=r"(r[2]), "=r"(r[3]) : "r"(a));
}
__device__ __forceinline__ void ldm_x4t(uint32_t* r, uint32_t a) {
    asm volatile("ldmatrix.sync.aligned.m8n8.x4.trans.shared.b16 {%0,%1,%2,%3}, [%4];"
                 : "=r"(r[0]), "=r"(r[1]), "=r"(r[2]), "=r"(r[3]) : "r"(a));
}
__device__ __forceinline__ void mma16816(float* c, const uint32_t* a, const uint32_t* b) {
    asm volatile("mma.sync.aligned.m16n8k16.row.col.f32.f16.f16.f32 "
                 "{%0,%1,%2,%3},{%4,%5,%6,%7},{%8,%9},{%0,%1,%2,%3};"
                 : "+f"(c[0]), "+f"(c[1]), "+f"(c[2]), "+f"(c[3])
                 : "r"(a[0]), "r"(a[1]), "r"(a[2]), "r"(a[3]), "r"(b[0]), "r"(b[1]));
}

// shared GEMM geometry
#define MB 128
#define NT 16
#define STG_BYTES 32768
#define SM_TOT (3 * STG_BYTES)

// ============================================================
// sq_gemm: g_B[seg 2z+1] = 2*A_z^2 - I
// ============================================================
__global__ void __launch_bounds__(256, 2)
sq_gemm()
{
    extern __shared__ char smem[];
    const uint32_t sb = smem_u32(smem);
    const int tid  = threadIdx.x;
    const int lane = tid & 31;
    const int wid  = tid >> 5;
    const int wm   = wid & 3;
    const int wn   = wid >> 2;
    const int bm   = blockIdx.y * MB;
    const int bn   = blockIdx.x * MB;
    const int z    = blockIdx.z;

    const __half* Xin = g_B  + (size_t)z * 2048 * NN;
    const __half* Ain = g_At + (size_t)z * NN * NN;
    __half* Out = g_B + ((size_t)z * 2048 + 1024) * NN;

    float acc[2][8][4];
#pragma unroll
    for (int t2 = 0; t2 < 2; t2++)
#pragma unroll
        for (int j = 0; j < 8; j++)
#pragma unroll
            for (int e = 0; e < 4; e++) acc[t2][j][e] = 0.0f;

    auto fill = [&](int t) {
        const int kt = t * 64;
        const uint32_t sa = sb + (t % 3) * STG_BYTES;
        const uint32_t sB = sa + 16384;
#pragma unroll
        for (int j = 0; j < 4; j++) {
            const int u = tid + j * 256;
            const int row = u >> 3, ch = u & 7;
            cp16(sa + row * 128 + ((ch ^ (row & 7)) << 4),
                 Xin + (size_t)(bm + row) * NN + kt + ch * 8);
        }
#pragma unroll
        for (int j = 0; j < 4; j++) {
            const int u = tid + j * 256;
            const int row = u >> 3, ch = u & 7;
            cp16(sB + row * 128 + ((ch ^ (row & 7)) << 4),
                 Ain + (size_t)(bn + row) * NN + kt + ch * 8);
        }
        asm volatile("cp.async.commit_group;" ::: "memory");
    };

    const int arow_l = (lane & 15);
    const int ach_l  = (lane >> 4);
    const int bgrp   = lane >> 3;
    const int brow_l = (lane & 7) + ((bgrp >> 1) << 3);
    const int bch_l  = (bgrp & 1);

    fill(0); fill(1);
    for (int t = 0; t < NT; t++) {
        if (t < NT - 1) asm volatile("cp.async.wait_group 1;" ::: "memory");
        else            asm volatile("cp.async.wait_group 0;" ::: "memory");
        __syncthreads();
        if (t + 2 < NT) fill(t + 2);

        const uint32_t sa = sb + (t % 3) * STG_BYTES;
        const uint32_t sB = sa + 16384;
#pragma unroll
        for (int ks = 0; ks < 4; ks++) {
            uint32_t afr[2][4];
#pragma unroll
            for (int t2 = 0; t2 < 2; t2++) {
                const int row = wm * 32 + t2 * 16 + arow_l;
                const int ch  = 2 * ks + ach_l;
                ldm_x4(afr[t2], sa + row * 128 + ((ch ^ (row & 7)) << 4));
            }
            uint32_t bfr[4][4];
#pragma unroll
            for (int tn = 0; tn < 4; tn++) {
                const int row = wn * 64 + tn * 16 + brow_l;
                const int ch  = 2 * ks + bch_l;
                ldm_x4(bfr[tn], sB + row * 128 + ((ch ^ (row & 7)) << 4));
            }
#pragma unroll
            for (int t2 = 0; t2 < 2; t2++)
#pragma unroll
                for (int j = 0; j < 8; j++)
                    mma16816(acc[t2][j], afr[t2], &bfr[j >> 1][(j & 1) * 2]);
        }
    }

    const int g  = lane >> 2;
    const int c2 = (lane & 3) * 2;
#pragma unroll
    for (int t2 = 0; t2 < 2; t2++)
#pragma unroll
        for (int j = 0; j < 8; j++) {
            const int col = bn + wn * 64 + j * 8 + c2;
#pragma unroll
            for (int half = 0; half < 2; half++) {
                const int row = bm + wm * 32 + t2 * 16 + g + half * 8;
                float v0 = acc[t2][j][half * 2 + 0];
                float v1 = acc[t2][j][half * 2 + 1];
                if (row == col)     v0 -= 1.0f;     // fold -I
                if (row == col + 1) v1 -= 1.0f;
                union { uint32_t u; __half h[2]; } Oh;
                Oh.h[0] = __float2half_rn(v0);
                Oh.h[1] = __float2half_rn(v1);
                *(uint32_t*)(Out + (size_t)row * NN + col) = Oh.u;
            }
        }
}

// ============================================================
// Wide GEMM into g_P — 4 warps (128 thr), warp tile 64x64.
// PART=0: segs {0,2}, grid (16,66). PART=1: segs {1,3}, grid (16,66).
// PART=2: all segs, grid (32,66).
// ============================================================
template<int PART>
__global__ void __launch_bounds__(128, 2)
gemm_wide(const __half* __restrict__ Xin, __half* __restrict__ Out)
{
    extern __shared__ char smem[];
    const uint32_t sb = smem_u32(smem);
    const int tid  = threadIdx.x;
    const int lane = tid & 31;
    const int wid  = tid >> 5;
    const int wm   = wid & 1;
    const int wn   = wid >> 1;
    const int bm   = blockIdx.y * MB;

    int bnG;
    if (PART == 0)      bnG = (blockIdx.x >> 3) * 2048 + (blockIdx.x & 7) * 128;
    else if (PART == 1) bnG = (blockIdx.x >> 3) * 2048 + 1024 + (blockIdx.x & 7) * 128;
    else                bnG = blockIdx.x * 128;

    float acc[4][8][4];
#pragma unroll
    for (int tm = 0; tm < 4; tm++)
#pragma unroll
        for (int j = 0; j < 8; j++)
#pragma unroll
            for (int e = 0; e < 4; e++) acc[tm][j][e] = 0.0f;

    auto fill = [&](int t) {
        const int kt = t * 64;
        const uint32_t sa = sb + (t % 3) * STG_BYTES;
        const uint32_t sB = sa + 16384;
#pragma unroll
        for (int j = 0; j < 8; j++) {
            const int u = tid + j * 128;
            const int row = u >> 3, ch = u & 7;
            cp16(sa + row * 128 + ((ch ^ (row & 7)) << 4),
                 Xin + (size_t)(bm + row) * NN + kt + ch * 8);
        }
#pragma unroll
        for (int j = 0; j < 8; j++) {
            const int u = tid + j * 128;
            const int row = u >> 3, ch = u & 7;
            cp16(sB + row * 128 + ((ch ^ (row & 7)) << 4),
                 g_B + (size_t)(bnG + row) * NN + kt + ch * 8);
        }
        asm volatile("cp.async.commit_group;" ::: "memory");
    };

    const int arow_l = (lane & 15);
    const int ach_l  = (lane >> 4);
    const int bgrp   = lane >> 3;
    const int brow_l = (lane & 7) + ((bgrp >> 1) << 3);
    const int bch_l  = (bgrp & 1);

    fill(0); fill(1);
    for (int t = 0; t < NT; t++) {
        if (t < NT - 1) asm volatile("cp.async.wait_group 1;" ::: "memory");
        else            asm volatile("cp.async.wait_group 0;" ::: "memory");
        __syncthreads();
        if (t + 2 < NT) fill(t + 2);

        const uint32_t sa = sb + (t % 3) * STG_BYTES;
        const uint32_t sB = sa + 16384;
#pragma unroll
        for (int ks = 0; ks < 4; ks++) {
            uint32_t afr[4][4];
#pragma unroll
            for (int tm = 0; tm < 4; tm++) {
                const int row = wm * 64 + tm * 16 + arow_l;
                const int ch  = 2 * ks + ach_l;
                ldm_x4(afr[tm], sa + row * 128 + ((ch ^ (row & 7)) << 4));
            }
            uint32_t bfr[4][4];
#pragma unroll
            for (int tn = 0; tn < 4; tn++) {
                const int row = wn * 64 + tn * 16 + brow_l;
                const int ch  = 2 * ks + bch_l;
                ldm_x4(bfr[tn], sB + row * 128 + ((ch ^ (row & 7)) << 4));
            }
#pragma unroll
            for (int tm = 0; tm < 4; tm++)
#pragma unroll
                for (int j = 0; j < 8; j++)
                    mma16816(acc[tm][j], afr[tm], &bfr[j >> 1][(j & 1) * 2]);
        }
    }

    const int g  = lane >> 2;
    const int c2 = (lane & 3) * 2;
#pragma unroll
    for (int tm = 0; tm < 4; tm++)
#pragma unroll
        for (int j = 0; j < 8; j++) {
            const int col = bnG + wn * 64 + j * 8 + c2;
#pragma unroll
            for (int half = 0; half < 2; half++) {
                const int row = bm + wm * 64 + tm * 16 + g + half * 8;
                union { uint32_t u; __half h[2]; } Oh;
                Oh.h[0] = __float2half_rn(acc[tm][j][half * 2 + 0]);
                Oh.h[1] = __float2half_rn(acc[tm][j][half * 2 + 1]);
                *(uint32_t*)(Out + (size_t)row * NWIDE + col) = Oh.u;
            }
        }
}

// ============================================================
// Projection via fp16 HMMA, K=336. Triple-buffer, 1 sync/iter.
// ============================================================
#define PKT 48
#define PNT 7
#define CSTR 132

template<int OTILE, int MODE>
__global__ void __launch_bounds__(256, 2)
proj_mma(const __half* __restrict__ Wsp, const float* __restrict__ bias,
         const __half* __restrict__ Xbase, const __half* __restrict__ Pbase,
         const __half* __restrict__ Uin, const float* __restrict__ hx,
         __half* __restrict__ Xout, __half* __restrict__ Uout,
         float* __restrict__ outp)
{
    constexpr int HS_B = PKT * 256;
    constexpr int WS_B = OTILE * 128;
    constexpr int STGP = HS_B + WS_B;
    constexpr int OW   = OTILE / 2;
    constexpr int NJ   = OW / 8;

    extern __shared__ char smem[];
    const uint32_t sb = smem_u32(smem);
    float* Cs = (float*)smem;

    const int tid  = threadIdx.x;
    const int lane = tid & 31;
    const int wid  = tid >> 5;
    const int wm   = wid & 3;
    const int wn   = wid >> 2;
    const int b    = blockIdx.y;
    const int bn0  = blockIdx.x * 128;

    float acc[2][NJ][4];
#pragma unroll
    for (int t2 = 0; t2 < 2; t2++)
#pragma unroll
        for (int j = 0; j < NJ; j++)
#pragma unroll
            for (int e = 0; e < 4; e++) acc[t2][j][e] = 0.0f;

    auto fill = [&](int t) {
        const int kt = t * PKT;
        const uint32_t hs = sb + (t % 3) * STGP;
        const uint32_t ws = hs + HS_B;
#pragma unroll
        for (int j = 0; j < 3; j++) {
            const int u = tid + j * 256;
            const int r = u >> 4, ch = u & 15;
            int c = kt + r;
            if (c >= 330) c = 0;
            const int p  = c / 66;
            const int cc = c - p * 66;
            const __half* gsrc;
            if (p == 0)
                gsrc = Xbase + ((size_t)b * CX + cc) * NN + bn0 + ch * 8;
            else
                gsrc = Pbase + ((size_t)b * CX + cc) * NWIDE + (size_t)(p - 1) * 1024
                     + bn0 + ch * 8;
            cp16(hs + r * 256 + ((ch ^ (r & 15)) << 4), gsrc);
        }
#pragma unroll
        for (int j = 0; j < (OTILE * 6 + 255) / 256; j++) {
            const int u = tid + j * 256;
            if (u < OTILE * 6) {
                const int orow = u / 6, wc = u - orow * 6;
                cp16(ws + orow * 128 + ((wc ^ (orow & 7)) << 4),
                     Wsp + (size_t)orow * 336 + kt + wc * 8);
            }
        }
        asm volatile("cp.async.commit_group;" ::: "memory");
    };

    const int krow_l = (lane & 7) + ((lane >> 4) << 3);
    const int m8sel  = (lane >> 3) & 1;
    const int bgrp   = lane >> 3;
    const int brow_l = (lane & 7) + ((bgrp >> 1) << 3);
    const int bch_l  = (bgrp & 1);

    fill(0); fill(1);
    for (int t = 0; t < PNT; t++) {
        if (t < PNT - 1) asm volatile("cp.async.wait_group 1;" ::: "memory");
        else             asm volatile("cp.async.wait_group 0;" ::: "memory");
        __syncthreads();
        if (t + 2 < PNT) fill(t + 2);

        const uint32_t hs = sb + (t % 3) * STGP;
        const uint32_t ws = hs + HS_B;
#pragma unroll
        for (int ks = 0; ks < 3; ks++) {
            uint32_t afr[2][4];
#pragma unroll
            for (int t2 = 0; t2 < 2; t2++) {
                const int kr  = ks * 16 + krow_l;
                const int chm = (wm * 4) + (t2 * 2) + m8sel;
                ldm_x4t(afr[t2], hs + kr * 256 + ((chm ^ (kr & 15)) << 4));
            }
            uint32_t bfr[NJ / 2 > 0 ? NJ / 2 : 1][4];
#pragma unroll
            for (int tn = 0; tn < NJ / 2; tn++) {
                const int row = wn * OW + tn * 16 + brow_l;
                const int ch  = 2 * ks + bch_l;
                ldm_x4(bfr[tn], ws + row * 128 + ((ch ^ (row & 7)) << 4));
            }
#pragma unroll
            for (int t2 = 0; t2 < 2; t2++)
#pragma unroll
                for (int j = 0; j < NJ; j++)
                    mma16816(acc[t2][j], afr[t2], &bfr[j >> 1][(j & 1) * 2]);
        }
    }

    __syncthreads();
    const int g  = lane >> 2;
    const int c2 = (lane & 3) * 2;
#pragma unroll
    for (int t2 = 0; t2 < 2; t2++)
#pragma unroll
        for (int j = 0; j < NJ; j++)
#pragma unroll
            for (int e = 0; e < 4; e++) {
                const int n = wm * 32 + t2 * 16 + g + (e >> 1) * 8;
                const int o = wn * OW + j * 8 + c2 + (e & 1);
                Cs[o * CSTR + n] = acc[t2][j][e];
            }
    __syncthreads();

    for (int o = wid; o < OTILE; o += 8) {
        const float bv = bias[o];
        const int n = lane * 4;
        float4 v = *(float4*)&Cs[o * CSTR + n];
        if (MODE == 0) {
            v.x = 1.0f / (1.0f + expf(-(v.x + bv)));
            v.y = 1.0f / (1.0f + expf(-(v.y + bv)));
            v.z = 1.0f / (1.0f + expf(-(v.z + bv)));
            v.w = 1.0f / (1.0f + expf(-(v.w + bv)));
            union { uint2 u2; __half h[4]; } O;
            if (o < HIDD) {
                const float4 h4 = *(const float4*)(hx + ((size_t)b * HIDD + o) * NN + bn0 + n);
                O.h[0] = __float2half_rn(v.x * h4.x);
                O.h[1] = __float2half_rn(v.y * h4.y);
                O.h[2] = __float2half_rn(v.z * h4.z);
                O.h[3] = __float2half_rn(v.w * h4.w);
                *(uint2*)(Xout + ((size_t)b * CX + INDIM + o) * NN + bn0 + n) = O.u2;
            } else {
                O.h[0] = __float2half_rn(v.x);
                O.h[1] = __float2half_rn(v.y);
                O.h[2] = __float2half_rn(v.z);
                O.h[3] = __float2half_rn(v.w);
                *(uint2*)(Uout + ((size_t)b * HIDD + (o - HIDD)) * NN + bn0 + n) = O.u2;
            }
        } else {
            union { uint2 u2; __half h[4]; } U;
            U.u2 = *(const uint2*)(Uin + ((size_t)b * HIDD + o) * NN + bn0 + n);
            const float4 h4 = *(const float4*)(hx + ((size_t)b * HIDD + o) * NN + bn0 + n);
            float4 r;
            const float u0 = __half2float(U.h[0]);
            const float u1 = __half2float(U.h[1]);
            const float u2 = __half2float(U.h[2]);
            const float u3 = __half2float(U.h[3]);
            r.x = u0 * h4.x + (1.0f - u0) * tanhf(v.x + bv);
            r.y = u1 * h4.y + (1.0f - u1) * tanhf(v.y + bv);
            r.z = u2 * h4.z + (1.0f - u2) * tanhf(v.z + bv);
            r.w = u3 * h4.w + (1.0f - u3) * tanhf(v.w + bv);
            *(float4*)(outp + ((size_t)b * HIDD + o) * NN + bn0 + n) = r;
        }
    }
}

// ============================================================
// prep kernels
// ============================================================
__global__ void prepA_kernel(const float* __restrict__ A0, const float* __restrict__ A1)
{
    __shared__ float ts[32][33];
    const int adj = blockIdx.z;
    const float* A = adj ? A1 : A0;
    const int x0 = blockIdx.x * 32;
    const int y0 = blockIdx.y * 32;
#pragma unroll
    for (int i = 0; i < 4; i++) {
        const int r = y0 + threadIdx.y + i * 8;
        const float v = A[(size_t)r * NN + x0 + threadIdx.x];
        ts[threadIdx.y + i * 8][threadIdx.x] = v;
        g_B[((size_t)adj * 2048 + r) * NN + x0 + threadIdx.x] = __float2half_rn(v);
    }
    __syncthreads();
#pragma unroll
    for (int i = 0; i < 4; i++) {
        const int r = x0 + threadIdx.y + i * 8;
        g_At[((size_t)adj * NN + r) * NN + y0 + threadIdx.x] =
            __float2half_rn(2.0f * ts[threadIdx.x][threadIdx.y + i * 8]);
    }
}

#define PK_ITEMS (MROWS * 256)
#define W_ITEMS  (192 * 336)

__global__ void pack1_kernel(const float* __restrict__ inputs, const float* __restrict__ hx,
                             const float* __restrict__ W_ru, const float* __restrict__ W_C)
{
    const int idx = blockIdx.x * blockDim.x + threadIdx.x;
    if (idx < PK_ITEMS) {
        const int n4 = idx & 255;
        const int t  = idx >> 8;
        const int c  = t % CX;
        const int b  = t / CX;
        float4 v;
        if (c < INDIM)
            v = ((const float4*)inputs)[((size_t)b * INDIM + c) * 256 + n4];
        else
            v = ((const float4*)hx)[((size_t)b * HIDD + (c - INDIM)) * 256 + n4];
        union { uint2 u; __half h[4]; } H;
        H.h[0] = __float2half_rn(v.x);
        H.h[1] = __float2half_rn(v.y);
        H.h[2] = __float2half_rn(v.z);
        H.h[3] = __float2half_rn(v.w);
        *(uint2*)(g_X + (size_t)t * NN + n4 * 4) = H.u;
    } else if (idx < PK_ITEMS + W_ITEMS) {
        const int k = idx - PK_ITEMS;
        const int o = k / 336;
        const int c = k - o * 336;
        float w = 0.0f;
        if (c < 330) w = (o < 128) ? W_ru[(size_t)o * 330 + c] : W_C[(size_t)(o - 128) * 330 + c];
        const __half h = __float2half_rn(w);
        if (o < 128) g_Wru[(size_t)o * 336 + c] = h;
        else         g_WC[(size_t)(o - 128) * 336 + c] = h;
    }
}

// ============================================================
extern "C" void kernel_launch(void* const* d_in, const int* in_sizes, int n_in,
                              void* d_out, int out_size)
{
    const float* inputs = (const float*)d_in[0];
    const float* hx     = (const float*)d_in[1];
    const float* A0     = (const float*)d_in[2];
    const float* A1     = (const float*)d_in[3];
    const float* W_ru   = (const float*)d_in[4];
    const float* b_ru   = (const float*)d_in[5];
    const float* W_C    = (const float*)d_in[6];
    const float* b_C    = (const float*)d_in[7];
    float* out = (float*)d_out;

    __half *gX, *gP, *gU, *gWru, *gWC;
    cudaGetSymbolAddress((void**)&gX,  g_X);
    cudaGetSymbolAddress((void**)&gP,  g_P);
    cudaGetSymbolAddress((void**)&gU,  g_U);
    cudaGetSymbolAddress((void**)&gWru, g_Wru);
    cudaGetSymbolAddress((void**)&gWC,  g_WC);

    static bool attr_set = false;
    static cudaStream_t s1;
    static cudaEvent_t evFork, evA, evPack, evG1;
    if (!attr_set) {
        cudaFuncSetAttribute(sq_gemm,      cudaFuncAttributeMaxDynamicSharedMemorySize, SM_TOT);
        cudaFuncSetAttribute(gemm_wide<0>, cudaFuncAttributeMaxDynamicSharedMemorySize, SM_TOT);
        cudaFuncSetAttribute(gemm_wide<1>, cudaFuncAttributeMaxDynamicSharedMemorySize, SM_TOT);
        cudaFuncSetAttribute(gemm_wide<2>, cudaFuncAttributeMaxDynamicSharedMemorySize, SM_TOT);
        const int p0 = 3 * (PKT * 256 + 128 * 128) > 128 * CSTR * 4
                     ? 3 * (PKT * 256 + 128 * 128) : 128 * CSTR * 4;       // 86016
        const int p1 = 3 * (PKT * 256 + 64 * 128) > 64 * CSTR * 4
                     ? 3 * (PKT * 256 + 64 * 128) : 64 * CSTR * 4;         // 61440
        cudaFuncSetAttribute(proj_mma<128, 0>, cudaFuncAttributeMaxDynamicSharedMemorySize, p0);
        cudaFuncSetAttribute(proj_mma<64, 1>,  cudaFuncAttributeMaxDynamicSharedMemorySize, p1);
        cudaStreamCreateWithFlags(&s1, cudaStreamNonBlocking);
        cudaEventCreateWithFlags(&evFork, cudaEventDisableTiming);
        cudaEventCreateWithFlags(&evA,    cudaEventDisableTiming);
        cudaEventCreateWithFlags(&evPack, cudaEventDisableTiming);
        cudaEventCreateWithFlags(&evG1,   cudaEventDisableTiming);
        attr_set = true;
    }
    const int smem0 = 3 * (PKT * 256 + 128 * 128) > 128 * CSTR * 4
                    ? 3 * (PKT * 256 + 128 * 128) : 128 * CSTR * 4;
    const int smem1 = 3 * (PKT * 256 + 64 * 128) > 64 * CSTR * 4
                    ? 3 * (PKT * 256 + 64 * 128) : 64 * CSTR * 4;

    const int packBlocks = (PK_ITEMS + W_ITEMS + 255) / 256;

    // Fork: origin -> evFork -> s1.
    cudaEventRecord(evFork, 0);
    cudaStreamWaitEvent(s1, evFork, 0);

    // s1: prepA -> [evA] -> sq_gemm -> (wait evPack) -> gw<1> -> [evG1]
    prepA_kernel<<<dim3(32, 32, 2), dim3(32, 8), 0, s1>>>(A0, A1);
    cudaEventRecord(evA, s1);
    sq_gemm<<<dim3(8, 8, 2), 256, SM_TOT, s1>>>();

    // main: pack1 -> [evPack]
    pack1_kernel<<<packBlocks, 256>>>(inputs, hx, W_ru, W_C);
    cudaEventRecord(evPack, 0);
    cudaStreamWaitEvent(s1, evPack, 0);

    // s1: gw<1> (segs 1,3: needs sq_gemm [s1 order] + pack1 [evPack])
    gemm_wide<1><<<dim3(16, MROWS / 128), 128, SM_TOT, s1>>>(gX, gP);
    cudaEventRecord(evG1, s1);

    // main: gw<0> (segs 0,2: needs prepA [evA] + pack1 [program order]).
    // Runs CONCURRENTLY with sq_gemm + gw<1> on s1.
    cudaStreamWaitEvent(0, evA, 0);
    gemm_wide<0><<<dim3(16, MROWS / 128), 128, SM_TOT>>>(gX, gP);

    // join before projection (needs all of g_P)
    cudaStreamWaitEvent(0, evG1, 0);

    // ---------- pass 1 projection: gates ----------
    proj_mma<128, 0><<<dim3(8, Bn), 256, smem0>>>(gWru, b_ru, gX, gP,
                                                  nullptr, hx, gX, gU, nullptr);

    // ---------- pass 2: candidate + output ----------
    gemm_wide<2><<<dim3(32, MROWS / 128), 128, SM_TOT>>>(gX, gP);
    proj_mma<64, 1><<<dim3(8, Bn), 256, smem1>>>(gWC, b_C, gX, gP,
                                                 gU, hx, nullptr, nullptr, out);
}

// round 17
// speedup vs baseline: 1.0725x; 1.0067x over previous
#include <cuda_runtime.h>
#include <cuda_fp16.h>
#include <math.h>
#include <stdint.h>

// Problem constants
#define Bn    128
#define HIDD  64
#define INDIM 2
#define CX    66
#define NN    1024
#define MROWS (Bn * CX)       // 8448
#define NWIDE 4096            // combined output width

// ---------------- scratch (device globals) ----------------
__device__ __half g_X  [MROWS * NN];           // X  (pass 1, fp16)
__device__ __half g_X2 [MROWS * NN];           // Xc (pass 2, fp16)
__device__ __half g_Pa [MROWS * NWIDE];        // pass-1 [P1|P2|P3|P4]
__device__ __half g_Pb [MROWS * NWIDE];        // pass-2 [P1|P2|P3|P4]
__device__ __half g_B  [NWIDE * NN];           // rows: A0 | 2A0^2-I | A1 | 2A1^2-I
__device__ __half g_At [2 * NN * NN];          // 2*A^T per adjacency
__device__ __half g_U  [Bn * HIDD * NN];       // u gate fp16
__device__ __half g_Wru[128 * 336];
__device__ __half g_WC [64 * 336];

// ---------------- PTX helpers (base ISA only) ----------------
__device__ __forceinline__ uint32_t smem_u32(const void* p) {
    uint32_t a;
    asm("{ .reg .u64 t; cvta.to.shared.u64 t, %1; cvt.u32.u64 %0, t; }" : "=r"(a) : "l"(p));
    return a;
}
__device__ __forceinline__ void cp16(uint32_t dst, const void* src) {
    asm volatile("cp.async.cg.shared.global [%0], [%1], 16;" :: "r"(dst), "l"(src) : "memory");
}
__device__ __forceinline__ void ldm_x4(uint32_t* r, uint32_t a) {
    asm volatile("ldmatrix.sync.aligned.m8n8.x4.shared.b16 {%0,%1,%2,%3}, [%4];"
                 : "=r"(r[0]), "=r"(r[1]), "=r"(r[2]), "=r"(r[3]) : "r"(a));
}
__device__ __forceinline__ void ldm_x4t(uint32_t* r, uint32_t a) {
    asm volatile("ldmatrix.sync.aligned.m8n8.x4.trans.shared.b16 {%0,%1,%2,%3}, [%4];"
                 : "=r"(r[0]), "=r"(r[1]), "=r"(r[2]), "=r"(r[3]) : "r"(a));
}
__device__ __forceinline__ void mma16816(float* c, const uint32_t* a, const uint32_t* b) {
    asm volatile("mma.sync.aligned.m16n8k16.row.col.f32.f16.f16.f32 "
                 "{%0,%1,%2,%3},{%4,%5,%6,%7},{%8,%9},{%0,%1,%2,%3};"
                 : "+f"(c[0]), "+f"(c[1]), "+f"(c[2]), "+f"(c[3])
                 : "r"(a[0]), "r"(a[1]), "r"(a[2]), "r"(a[3]), "r"(b[0]), "r"(b[1]));
}

// shared GEMM geometry
#define MB 128
#define NT 16
#define STG_BYTES 32768
#define SM_TOT (3 * STG_BYTES)

// ============================================================
// sq_gemm: g_B[seg 2z+1] = 2*A_z^2 - I
// ============================================================
__global__ void __launch_bounds__(256, 2)
sq_gemm()
{
    extern __shared__ char smem[];
    const uint32_t sb = smem_u32(smem);
    const int tid  = threadIdx.x;
    const int lane = tid & 31;
    const int wid  = tid >> 5;
    const int wm   = wid & 3;
    const int wn   = wid >> 2;
    const int bm   = blockIdx.y * MB;
    const int bn   = blockIdx.x * MB;
    const int z    = blockIdx.z;

    const __half* Xin = g_B  + (size_t)z * 2048 * NN;
    const __half* Ain = g_At + (size_t)z * NN * NN;
    __half* Out = g_B + ((size_t)z * 2048 + 1024) * NN;

    float acc[2][8][4];
#pragma unroll
    for (int t2 = 0; t2 < 2; t2++)
#pragma unroll
        for (int j = 0; j < 8; j++)
#pragma unroll
            for (int e = 0; e < 4; e++) acc[t2][j][e] = 0.0f;

    auto fill = [&](int t) {
        const int kt = t * 64;
        const uint32_t sa = sb + (t % 3) * STG_BYTES;
        const uint32_t sB = sa + 16384;
#pragma unroll
        for (int j = 0; j < 4; j++) {
            const int u = tid + j * 256;
            const int row = u >> 3, ch = u & 7;
            cp16(sa + row * 128 + ((ch ^ (row & 7)) << 4),
                 Xin + (size_t)(bm + row) * NN + kt + ch * 8);
        }
#pragma unroll
        for (int j = 0; j < 4; j++) {
            const int u = tid + j * 256;
            const int row = u >> 3, ch = u & 7;
            cp16(sB + row * 128 + ((ch ^ (row & 7)) << 4),
                 Ain + (size_t)(bn + row) * NN + kt + ch * 8);
        }
        asm volatile("cp.async.commit_group;" ::: "memory");
    };

    const int arow_l = (lane & 15);
    const int ach_l  = (lane >> 4);
    const int bgrp   = lane >> 3;
    const int brow_l = (lane & 7) + ((bgrp >> 1) << 3);
    const int bch_l  = (bgrp & 1);

    fill(0); fill(1);
    for (int t = 0; t < NT; t++) {
        if (t < NT - 1) asm volatile("cp.async.wait_group 1;" ::: "memory");
        else            asm volatile("cp.async.wait_group 0;" ::: "memory");
        __syncthreads();
        if (t + 2 < NT) fill(t + 2);

        const uint32_t sa = sb + (t % 3) * STG_BYTES;
        const uint32_t sB = sa + 16384;
#pragma unroll
        for (int ks = 0; ks < 4; ks++) {
            uint32_t afr[2][4];
#pragma unroll
            for (int t2 = 0; t2 < 2; t2++) {
                const int row = wm * 32 + t2 * 16 + arow_l;
                const int ch  = 2 * ks + ach_l;
                ldm_x4(afr[t2], sa + row * 128 + ((ch ^ (row & 7)) << 4));
            }
            uint32_t bfr[4][4];
#pragma unroll
            for (int tn = 0; tn < 4; tn++) {
                const int row = wn * 64 + tn * 16 + brow_l;
                const int ch  = 2 * ks + bch_l;
                ldm_x4(bfr[tn], sB + row * 128 + ((ch ^ (row & 7)) << 4));
            }
#pragma unroll
            for (int t2 = 0; t2 < 2; t2++)
#pragma unroll
                for (int j = 0; j < 8; j++)
                    mma16816(acc[t2][j], afr[t2], &bfr[j >> 1][(j & 1) * 2]);
        }
    }

    const int g  = lane >> 2;
    const int c2 = (lane & 3) * 2;
#pragma unroll
    for (int t2 = 0; t2 < 2; t2++)
#pragma unroll
        for (int j = 0; j < 8; j++) {
            const int col = bn + wn * 64 + j * 8 + c2;
#pragma unroll
            for (int half = 0; half < 2; half++) {
                const int row = bm + wm * 32 + t2 * 16 + g + half * 8;
                float v0 = acc[t2][j][half * 2 + 0];
                float v1 = acc[t2][j][half * 2 + 1];
                if (row == col)     v0 -= 1.0f;     // fold -I
                if (row == col + 1) v1 -= 1.0f;
                union { uint32_t u; __half h[2]; } Oh;
                Oh.h[0] = __float2half_rn(v0);
                Oh.h[1] = __float2half_rn(v1);
                *(uint32_t*)(Out + (size_t)row * NN + col) = Oh.u;
            }
        }
}

// ============================================================
// Wide GEMM — 4 warps (128 thr), warp tile 64x64.
// PART=0: segs {0,2}, grid (16,66). PART=1: segs {1,3}, grid (16,66).
// PART=2: all segs, grid (32,66).
// ============================================================
template<int PART>
__global__ void __launch_bounds__(128, 2)
gemm_wide(const __half* __restrict__ Xin, __half* __restrict__ Out)
{
    extern __shared__ char smem[];
    const uint32_t sb = smem_u32(smem);
    const int tid  = threadIdx.x;
    const int lane = tid & 31;
    const int wid  = tid >> 5;
    const int wm   = wid & 1;
    const int wn   = wid >> 1;
    const int bm   = blockIdx.y * MB;

    int bnG;
    if (PART == 0)      bnG = (blockIdx.x >> 3) * 2048 + (blockIdx.x & 7) * 128;
    else if (PART == 1) bnG = (blockIdx.x >> 3) * 2048 + 1024 + (blockIdx.x & 7) * 128;
    else                bnG = blockIdx.x * 128;

    float acc[4][8][4];
#pragma unroll
    for (int tm = 0; tm < 4; tm++)
#pragma unroll
        for (int j = 0; j < 8; j++)
#pragma unroll
            for (int e = 0; e < 4; e++) acc[tm][j][e] = 0.0f;

    auto fill = [&](int t) {
        const int kt = t * 64;
        const uint32_t sa = sb + (t % 3) * STG_BYTES;
        const uint32_t sB = sa + 16384;
#pragma unroll
        for (int j = 0; j < 8; j++) {
            const int u = tid + j * 128;
            const int row = u >> 3, ch = u & 7;
            cp16(sa + row * 128 + ((ch ^ (row & 7)) << 4),
                 Xin + (size_t)(bm + row) * NN + kt + ch * 8);
        }
#pragma unroll
        for (int j = 0; j < 8; j++) {
            const int u = tid + j * 128;
            const int row = u >> 3, ch = u & 7;
            cp16(sB + row * 128 + ((ch ^ (row & 7)) << 4),
                 g_B + (size_t)(bnG + row) * NN + kt + ch * 8);
        }
        asm volatile("cp.async.commit_group;" ::: "memory");
    };

    const int arow_l = (lane & 15);
    const int ach_l  = (lane >> 4);
    const int bgrp   = lane >> 3;
    const int brow_l = (lane & 7) + ((bgrp >> 1) << 3);
    const int bch_l  = (bgrp & 1);

    fill(0); fill(1);
    for (int t = 0; t < NT; t++) {
        if (t < NT - 1) asm volatile("cp.async.wait_group 1;" ::: "memory");
        else            asm volatile("cp.async.wait_group 0;" ::: "memory");
        __syncthreads();
        if (t + 2 < NT) fill(t + 2);

        const uint32_t sa = sb + (t % 3) * STG_BYTES;
        const uint32_t sB = sa + 16384;
#pragma unroll
        for (int ks = 0; ks < 4; ks++) {
            uint32_t afr[4][4];
#pragma unroll
            for (int tm = 0; tm < 4; tm++) {
                const int row = wm * 64 + tm * 16 + arow_l;
                const int ch  = 2 * ks + ach_l;
                ldm_x4(afr[tm], sa + row * 128 + ((ch ^ (row & 7)) << 4));
            }
            uint32_t bfr[4][4];
#pragma unroll
            for (int tn = 0; tn < 4; tn++) {
                const int row = wn * 64 + tn * 16 + brow_l;
                const int ch  = 2 * ks + bch_l;
                ldm_x4(bfr[tn], sB + row * 128 + ((ch ^ (row & 7)) << 4));
            }
#pragma unroll
            for (int tm = 0; tm < 4; tm++)
#pragma unroll
                for (int j = 0; j < 8; j++)
                    mma16816(acc[tm][j], afr[tm], &bfr[j >> 1][(j & 1) * 2]);
        }
    }

    const int g  = lane >> 2;
    const int c2 = (lane & 3) * 2;
#pragma unroll
    for (int tm = 0; tm < 4; tm++)
#pragma unroll
        for (int j = 0; j < 8; j++) {
            const int col = bnG + wn * 64 + j * 8 + c2;
#pragma unroll
            for (int half = 0; half < 2; half++) {
                const int row = bm + wm * 64 + tm * 16 + g + half * 8;
                union { uint32_t u; __half h[2]; } Oh;
                Oh.h[0] = __float2half_rn(acc[tm][j][half * 2 + 0]);
                Oh.h[1] = __float2half_rn(acc[tm][j][half * 2 + 1]);
                *(uint32_t*)(Out + (size_t)row * NWIDE + col) = Oh.u;
            }
        }
}

// ============================================================
// Projection via fp16 HMMA, K=336. Triple-buffer, 1 sync/iter.
// MODE 0: r-gate  — write r*hx (fp16) into Xout channels 2..65.
// MODE 1: final   — out = u*hx + (1-u)*tanh(W@H+b), fp32.
// MODE 2: u-gate  — write u (fp16) into Uout.
// All OTILE=64.
// ============================================================
#define PKT 48
#define PNT 7
#define CSTR 132

template<int MODE>
__global__ void __launch_bounds__(256, 2)
proj_mma(const __half* __restrict__ Wsp, const float* __restrict__ bias,
         const __half* __restrict__ Xbase, const __half* __restrict__ Pbase,
         const __half* __restrict__ Uin, const float* __restrict__ hx,
         __half* __restrict__ Xout, __half* __restrict__ Uout,
         float* __restrict__ outp)
{
    constexpr int OTILE = 64;
    constexpr int HS_B = PKT * 256;
    constexpr int WS_B = OTILE * 128;
    constexpr int STGP = HS_B + WS_B;
    constexpr int OW   = OTILE / 2;
    constexpr int NJ   = OW / 8;

    extern __shared__ char smem[];
    const uint32_t sb = smem_u32(smem);
    float* Cs = (float*)smem;

    const int tid  = threadIdx.x;
    const int lane = tid & 31;
    const int wid  = tid >> 5;
    const int wm   = wid & 3;
    const int wn   = wid >> 2;
    const int b    = blockIdx.y;
    const int bn0  = blockIdx.x * 128;

    float acc[2][NJ][4];
#pragma unroll
    for (int t2 = 0; t2 < 2; t2++)
#pragma unroll
        for (int j = 0; j < NJ; j++)
#pragma unroll
            for (int e = 0; e < 4; e++) acc[t2][j][e] = 0.0f;

    auto fill = [&](int t) {
        const int kt = t * PKT;
        const uint32_t hs = sb + (t % 3) * STGP;
        const uint32_t ws = hs + HS_B;
#pragma unroll
        for (int j = 0; j < 3; j++) {
            const int u = tid + j * 256;
            const int r = u >> 4, ch = u & 15;
            int c = kt + r;
            if (c >= 330) c = 0;
            const int p  = c / 66;
            const int cc = c - p * 66;
            const __half* gsrc;
            if (p == 0)
                gsrc = Xbase + ((size_t)b * CX + cc) * NN + bn0 + ch * 8;
            else
                gsrc = Pbase + ((size_t)b * CX + cc) * NWIDE + (size_t)(p - 1) * 1024
                     + bn0 + ch * 8;
            cp16(hs + r * 256 + ((ch ^ (r & 15)) << 4), gsrc);
        }
#pragma unroll
        for (int j = 0; j < (OTILE * 6 + 255) / 256; j++) {
            const int u = tid + j * 256;
            if (u < OTILE * 6) {
                const int orow = u / 6, wc = u - orow * 6;
                cp16(ws + orow * 128 + ((wc ^ (orow & 7)) << 4),
                     Wsp + (size_t)orow * 336 + kt + wc * 8);
            }
        }
        asm volatile("cp.async.commit_group;" ::: "memory");
    };

    const int krow_l = (lane & 7) + ((lane >> 4) << 3);
    const int m8sel  = (lane >> 3) & 1;
    const int bgrp   = lane >> 3;
    const int brow_l = (lane & 7) + ((bgrp >> 1) << 3);
    const int bch_l  = (bgrp & 1);

    fill(0); fill(1);
    for (int t = 0; t < PNT; t++) {
        if (t < PNT - 1) asm volatile("cp.async.wait_group 1;" ::: "memory");
        else             asm volatile("cp.async.wait_group 0;" ::: "memory");
        __syncthreads();
        if (t + 2 < PNT) fill(t + 2);

        const uint32_t hs = sb + (t % 3) * STGP;
        const uint32_t ws = hs + HS_B;
#pragma unroll
        for (int ks = 0; ks < 3; ks++) {
            uint32_t afr[2][4];
#pragma unroll
            for (int t2 = 0; t2 < 2; t2++) {
                const int kr  = ks * 16 + krow_l;
                const int chm = (wm * 4) + (t2 * 2) + m8sel;
                ldm_x4t(afr[t2], hs + kr * 256 + ((chm ^ (kr & 15)) << 4));
            }
            uint32_t bfr[NJ / 2 > 0 ? NJ / 2 : 1][4];
#pragma unroll
            for (int tn = 0; tn < NJ / 2; tn++) {
                const int row = wn * OW + tn * 16 + brow_l;
                const int ch  = 2 * ks + bch_l;
                ldm_x4(bfr[tn], ws + row * 128 + ((ch ^ (row & 7)) << 4));
            }
#pragma unroll
            for (int t2 = 0; t2 < 2; t2++)
#pragma unroll
                for (int j = 0; j < NJ; j++)
                    mma16816(acc[t2][j], afr[t2], &bfr[j >> 1][(j & 1) * 2]);
        }
    }

    __syncthreads();
    const int g  = lane >> 2;
    const int c2 = (lane & 3) * 2;
#pragma unroll
    for (int t2 = 0; t2 < 2; t2++)
#pragma unroll
        for (int j = 0; j < NJ; j++)
#pragma unroll
            for (int e = 0; e < 4; e++) {
                const int n = wm * 32 + t2 * 16 + g + (e >> 1) * 8;
                const int o = wn * OW + j * 8 + c2 + (e & 1);
                Cs[o * CSTR + n] = acc[t2][j][e];
            }
    __syncthreads();

    for (int o = wid; o < OTILE; o += 8) {
        const float bv = bias[o];
        const int n = lane * 4;
        float4 v = *(float4*)&Cs[o * CSTR + n];
        if (MODE == 0) {
            // r gate -> r*hx into Xout channels
            v.x = 1.0f / (1.0f + expf(-(v.x + bv)));
            v.y = 1.0f / (1.0f + expf(-(v.y + bv)));
            v.z = 1.0f / (1.0f + expf(-(v.z + bv)));
            v.w = 1.0f / (1.0f + expf(-(v.w + bv)));
            const float4 h4 = *(const float4*)(hx + ((size_t)b * HIDD + o) * NN + bn0 + n);
            union { uint2 u2; __half h[4]; } O;
            O.h[0] = __float2half_rn(v.x * h4.x);
            O.h[1] = __float2half_rn(v.y * h4.y);
            O.h[2] = __float2half_rn(v.z * h4.z);
            O.h[3] = __float2half_rn(v.w * h4.w);
            *(uint2*)(Xout + ((size_t)b * CX + INDIM + o) * NN + bn0 + n) = O.u2;
        } else if (MODE == 2) {
            // u gate -> Uout
            v.x = 1.0f / (1.0f + expf(-(v.x + bv)));
            v.y = 1.0f / (1.0f + expf(-(v.y + bv)));
            v.z = 1.0f / (1.0f + expf(-(v.z + bv)));
            v.w = 1.0f / (1.0f + expf(-(v.w + bv)));
            union { uint2 u2; __half h[4]; } O;
            O.h[0] = __float2half_rn(v.x);
            O.h[1] = __float2half_rn(v.y);
            O.h[2] = __float2half_rn(v.z);
            O.h[3] = __float2half_rn(v.w);
            *(uint2*)(Uout + ((size_t)b * HIDD + o) * NN + bn0 + n) = O.u2;
        } else {
            union { uint2 u2; __half h[4]; } U;
            U.u2 = *(const uint2*)(Uin + ((size_t)b * HIDD + o) * NN + bn0 + n);
            const float4 h4 = *(const float4*)(hx + ((size_t)b * HIDD + o) * NN + bn0 + n);
            float4 r;
            const float u0 = __half2float(U.h[0]);
            const float u1 = __half2float(U.h[1]);
            const float u2 = __half2float(U.h[2]);
            const float u3 = __half2float(U.h[3]);
            r.x = u0 * h4.x + (1.0f - u0) * tanhf(v.x + bv);
            r.y = u1 * h4.y + (1.0f - u1) * tanhf(v.y + bv);
            r.z = u2 * h4.z + (1.0f - u2) * tanhf(v.z + bv);
            r.w = u3 * h4.w + (1.0f - u3) * tanhf(v.w + bv);
            *(float4*)(outp + ((size_t)b * HIDD + o) * NN + bn0 + n) = r;
        }
    }
}

// ============================================================
// prep kernels
// ============================================================
__global__ void prepA_kernel(const float* __restrict__ A0, const float* __restrict__ A1)
{
    __shared__ float ts[32][33];
    const int adj = blockIdx.z;
    const float* A = adj ? A1 : A0;
    const int x0 = blockIdx.x * 32;
    const int y0 = blockIdx.y * 32;
#pragma unroll
    for (int i = 0; i < 4; i++) {
        const int r = y0 + threadIdx.y + i * 8;
        const float v = A[(size_t)r * NN + x0 + threadIdx.x];
        ts[threadIdx.y + i * 8][threadIdx.x] = v;
        g_B[((size_t)adj * 2048 + r) * NN + x0 + threadIdx.x] = __float2half_rn(v);
    }
    __syncthreads();
#pragma unroll
    for (int i = 0; i < 4; i++) {
        const int r = x0 + threadIdx.y + i * 8;
        g_At[((size_t)adj * NN + r) * NN + y0 + threadIdx.x] =
            __float2half_rn(2.0f * ts[threadIdx.x][threadIdx.y + i * 8]);
    }
}

#define PK_ITEMS (MROWS * 256)
#define W_ITEMS  (192 * 336)

__global__ void pack1_kernel(const float* __restrict__ inputs, const float* __restrict__ hx,
                             const float* __restrict__ W_ru, const float* __restrict__ W_C)
{
    const int idx = blockIdx.x * blockDim.x + threadIdx.x;
    if (idx < PK_ITEMS) {
        const int n4 = idx & 255;
        const int t  = idx >> 8;
        const int c  = t % CX;
        const int b  = t / CX;
        float4 v;
        if (c < INDIM)
            v = ((const float4*)inputs)[((size_t)b * INDIM + c) * 256 + n4];
        else
            v = ((const float4*)hx)[((size_t)b * HIDD + (c - INDIM)) * 256 + n4];
        union { uint2 u; __half h[4]; } H;
        H.h[0] = __float2half_rn(v.x);
        H.h[1] = __float2half_rn(v.y);
        H.h[2] = __float2half_rn(v.z);
        H.h[3] = __float2half_rn(v.w);
        *(uint2*)(g_X + (size_t)t * NN + n4 * 4) = H.u;
        if (c < INDIM)   // Xc buffer shares input channels
            *(uint2*)(g_X2 + (size_t)t * NN + n4 * 4) = H.u;
    } else if (idx < PK_ITEMS + W_ITEMS) {
        const int k = idx - PK_ITEMS;
        const int o = k / 336;
        const int c = k - o * 336;
        float w = 0.0f;
        if (c < 330) w = (o < 128) ? W_ru[(size_t)o * 330 + c] : W_C[(size_t)(o - 128) * 330 + c];
        const __half h = __float2half_rn(w);
        if (o < 128) g_Wru[(size_t)o * 336 + c] = h;
        else         g_WC[(size_t)(o - 128) * 336 + c] = h;
    }
}

// ============================================================
extern "C" void kernel_launch(void* const* d_in, const int* in_sizes, int n_in,
                              void* d_out, int out_size)
{
    const float* inputs = (const float*)d_in[0];
    const float* hx     = (const float*)d_in[1];
    const float* A0     = (const float*)d_in[2];
    const float* A1     = (const float*)d_in[3];
    const float* W_ru   = (const float*)d_in[4];
    const float* b_ru   = (const float*)d_in[5];
    const float* W_C    = (const float*)d_in[6];
    const float* b_C    = (const float*)d_in[7];
    float* out = (float*)d_out;

    __half *gX, *gX2, *gPa, *gPb, *gU, *gWru, *gWC;
    cudaGetSymbolAddress((void**)&gX,   g_X);
    cudaGetSymbolAddress((void**)&gX2,  g_X2);
    cudaGetSymbolAddress((void**)&gPa,  g_Pa);
    cudaGetSymbolAddress((void**)&gPb,  g_Pb);
    cudaGetSymbolAddress((void**)&gU,   g_U);
    cudaGetSymbolAddress((void**)&gWru, g_Wru);
    cudaGetSymbolAddress((void**)&gWC,  g_WC);

    static bool attr_set = false;
    static cudaStream_t s1;
    static cudaEvent_t evFork, evA, evPack, evG1, evG0, evU;
    if (!attr_set) {
        cudaFuncSetAttribute(sq_gemm,      cudaFuncAttributeMaxDynamicSharedMemorySize, SM_TOT);
        cudaFuncSetAttribute(gemm_wide<0>, cudaFuncAttributeMaxDynamicSharedMemorySize, SM_TOT);
        cudaFuncSetAttribute(gemm_wide<1>, cudaFuncAttributeMaxDynamicSharedMemorySize, SM_TOT);
        cudaFuncSetAttribute(gemm_wide<2>, cudaFuncAttributeMaxDynamicSharedMemorySize, SM_TOT);
        const int p1 = 3 * (PKT * 256 + 64 * 128) > 64 * CSTR * 4
                     ? 3 * (PKT * 256 + 64 * 128) : 64 * CSTR * 4;         // 61440
        cudaFuncSetAttribute(proj_mma<0>, cudaFuncAttributeMaxDynamicSharedMemorySize, p1);
        cudaFuncSetAttribute(proj_mma<1>, cudaFuncAttributeMaxDynamicSharedMemorySize, p1);
        cudaFuncSetAttribute(proj_mma<2>, cudaFuncAttributeMaxDynamicSharedMemorySize, p1);
        cudaStreamCreateWithFlags(&s1, cudaStreamNonBlocking);
        cudaEventCreateWithFlags(&evFork, cudaEventDisableTiming);
        cudaEventCreateWithFlags(&evA,    cudaEventDisableTiming);
        cudaEventCreateWithFlags(&evPack, cudaEventDisableTiming);
        cudaEventCreateWithFlags(&evG1,   cudaEventDisableTiming);
        cudaEventCreateWithFlags(&evG0,   cudaEventDisableTiming);
        cudaEventCreateWithFlags(&evU,    cudaEventDisableTiming);
        attr_set = true;
    }
    const int smemP = 3 * (PKT * 256 + 64 * 128) > 64 * CSTR * 4
                    ? 3 * (PKT * 256 + 64 * 128) : 64 * CSTR * 4;

    const int packBlocks = (PK_ITEMS + W_ITEMS + 255) / 256;

    // Fork: origin -> evFork -> s1.
    cudaEventRecord(evFork, 0);
    cudaStreamWaitEvent(s1, evFork, 0);

    // s1: prepA -> [evA] -> sq_gemm -> (wait evPack) -> gw<1> -> [evG1]
    prepA_kernel<<<dim3(32, 32, 2), dim3(32, 8), 0, s1>>>(A0, A1);
    cudaEventRecord(evA, s1);
    sq_gemm<<<dim3(8, 8, 2), 256, SM_TOT, s1>>>();

    // main: pack1 -> [evPack]
    pack1_kernel<<<packBlocks, 256>>>(inputs, hx, W_ru, W_C);
    cudaEventRecord(evPack, 0);
    cudaStreamWaitEvent(s1, evPack, 0);

    // s1: gw<1> (segs 1,3 of pass 1)
    gemm_wide<1><<<dim3(16, MROWS / 128), 128, SM_TOT, s1>>>(gX, gPa);
    cudaEventRecord(evG1, s1);

    // main: gw<0> (segs 0,2) — concurrent with sq_gemm+gw<1>
    cudaStreamWaitEvent(0, evA, 0);
    gemm_wide<0><<<dim3(16, MROWS / 128), 128, SM_TOT>>>(gX, gPa);
    cudaEventRecord(evG0, 0);

    // join pass-1 GEMMs on main for proj_r
    cudaStreamWaitEvent(0, evG1, 0);
    // proj_r: reads gX+gPa, writes gX2 channels 2..65 (critical path)
    proj_mma<0><<<dim3(8, Bn), 256, smemP>>>(gWru, b_ru, gX, gPa,
                                             nullptr, hx, gX2, nullptr, nullptr);

    // s1: proj_u — reads gX+gPa (untouched), writes gU; hides under gw<2>
    cudaStreamWaitEvent(s1, evG0, 0);
    proj_mma<2><<<dim3(8, Bn), 256, smemP, s1>>>(gWru + (size_t)64 * 336, b_ru + 64,
                                                 gX, gPa, nullptr, hx,
                                                 nullptr, gU, nullptr);
    cudaEventRecord(evU, s1);

    // main: pass-2 GEMM (reads gX2, writes gPb — no conflict with proj_u)
    gemm_wide<2><<<dim3(32, MROWS / 128), 128, SM_TOT>>>(gX2, gPb);

    // final projection needs gU
    cudaStreamWaitEvent(0, evU, 0);
    proj_mma<1><<<dim3(8, Bn), 256, smemP>>>(gWC, b_C, gX2, gPb,
                                             gU, hx, nullptr, nullptr, out);
}